// round 5
// baseline (speedup 1.0000x reference)
#include <cuda_runtime.h>

#define N_POS   1024
#define BDIM    256
#define SPLIT   16
#define NBLK    (64 * SPLIT)   // 1024
#define KTOP    10
#define NWARP   (BDIM / 32)

__device__ float    g_partial[NBLK];
__device__ int      g_count[NBLK];
__device__ unsigned g_ticket;   // zero-init; reset to 0 by the last block each launch

// idcg prefix table: idcg(kk) = sum_{k=0}^{kk-1} 1/log2(k+2), kk = min(nrel, 10)
__constant__ float c_idcg[11] = {
    0.0f, 1.0f, 1.6309297535714574f, 2.1309297535714574f,
    2.5616063116448505f, 2.9484591188793920f, 3.3046663059874144f,
    3.6379996393207477f, 3.9534645161064764f, 4.2544945117704580f,
    4.5435593380883460f
};

__global__ __launch_bounds__(BDIM, 6) void lambdarank_fused(
    const float* __restrict__ scores, const int* __restrict__ rels,
    float* __restrict__ out)
{
    // float4-aligned compacted lists; float2 views for the compaction scatter
    __shared__ float4 relSD4[(N_POS + 64) / 2];   // (e^{-si}, disc_i) pairs
    __shared__ float4 nonSD4[(N_POS + 128) / 2];  // (e^{+sj}, disc_j) pairs
    __shared__ float  s_score[N_POS];
    __shared__ int    s_rel[N_POS];
    __shared__ int    sh_cntR[NWARP], sh_baseR[NWARP], sh_baseN[NWARP];
    __shared__ int    sh_tot[2];
    __shared__ float  red_f[NWARP];
    __shared__ int    red_i[NWARP];
    __shared__ bool   s_last;

    float2* relSD = (float2*)relSD4;
    float2* nonSD = (float2*)nonSD4;

    const int b    = blockIdx.x >> 4;          // SPLIT = 16
    const int s    = blockIdx.x & (SPLIT - 1);
    const int t    = threadIdx.x;
    const int lane = t & 31;
    const int wid  = t >> 5;
    const unsigned lt_mask = (1u << lane) - 1u;

    // ---- Stage this batch's row (vectorized, coalesced) ----
    {
        const float4* sc4 = (const float4*)(scores + (size_t)b * N_POS);
        const int4*   rl4 = (const int4*)(rels   + (size_t)b * N_POS);
        for (int p = t; p < N_POS / 4; p += BDIM) {
            ((float4*)s_score)[p] = sc4[p];
            ((int4*)s_rel)[p]     = rl4[p];
        }
    }
    __syncthreads();

    // ---- Parallel deterministic stable compaction (all 8 warps) ----
    unsigned masks[4];
    {
        int cr = 0;
        #pragma unroll
        for (int it = 0; it < 4; it++) {
            int p = (wid << 7) + (it << 5) + lane;
            unsigned m = __ballot_sync(0xffffffffu, s_rel[p] != 0);
            masks[it] = m;
            cr += __popc(m);
        }
        if (lane == 0) sh_cntR[wid] = cr;
    }
    __syncthreads();
    if (t == 0) {
        int aR = 0, aN = 0;
        #pragma unroll
        for (int w = 0; w < NWARP; w++) {
            sh_baseR[w] = aR; sh_baseN[w] = aN;
            aR += sh_cntR[w]; aN += 128 - sh_cntR[w];
        }
        sh_tot[0] = aR; sh_tot[1] = aN;
    }
    __syncthreads();
    {
        int rb = sh_baseR[wid], nb = sh_baseN[wid];
        #pragma unroll
        for (int it = 0; it < 4; it++) {
            int p = (wid << 7) + (it << 5) + lane;
            unsigned m = masks[it];
            bool hit = (m >> lane) & 1u;
            float sc = s_score[p];
            float E  = __expf(hit ? -sc : sc);
            float d  = 1.0f / __log2f((float)p + 2.0f);   // DCG discount @ position p
            float2 v = make_float2(E, d);
            int preR = __popc(m & lt_mask);
            if (hit) relSD[rb + preR]          = v;
            else     nonSD[nb + (lane - preR)] = v;
            rb += __popc(m);
            nb += 32 - __popc(m);
        }
    }
    __syncthreads();

    const int nrel = sh_tot[0];
    const int nnon = sh_tot[1];

    // Zero padding: E=0 entries contribute exactly 0 (log2(1+0)=0, w*0=0)
    if (t < 64)  relSD[nrel + t] = make_float2(0.0f, 0.0f);
    if (t < 128) nonSD[nnon + t] = make_float2(0.0f, 0.0f);
    __syncthreads();

    float thread_sum = 0.0f;
    int   blk_count  = 0;

    if (nrel > 0 && nnon > 0) {
        const float idcg = c_idcg[(nrel < KTOP) ? nrel : KTOP];
        const float norm = 0.69314718055994531f / (idcg + 1e-8f);  // ln2/(idcg+eps)

        // Contiguous, even-aligned j-chunk per block
        const int chunk = ((((nnon + SPLIT - 1) >> 4) + 1) & ~1);
        const int j0    = s * chunk;
        int cntj  = nnon - j0;
        cntj  = (cntj < 0) ? 0 : ((cntj > chunk) ? chunk : cntj);
        blk_count = nrel * cntj;

        const int trips4 = (cntj + 1) >> 1;              // float4 loads (2 j's each)
        const float4* nj4 = (const float4*)&nonSD[j0];   // j0 even -> 16B aligned

        if (trips4 > 0) {
            for (int ibase = 0; ibase < nrel; ibase += 2 * BDIM) {
                if (ibase + (wid << 6) >= nrel) continue;     // whole-warp tail skip
                const int ia = ibase + 2 * t;                 // zero-pad covers overhang
                const float4 rv = relSD4[ia >> 1];
                const float Ei0 = rv.x, di0 = rv.y;
                const float Ei1 = rv.z, di1 = rv.w;

                float a0 = 0.0f, a1 = 0.0f, a2 = 0.0f, a3 = 0.0f;
                #pragma unroll 4
                for (int k = 0; k < trips4; k++) {
                    const float4 nd = nj4[k];                 // 2 j's per LDS.128
                    float u00 = fmaf(nd.x, Ei0, 1.0f);
                    float u10 = fmaf(nd.x, Ei1, 1.0f);
                    float u01 = fmaf(nd.z, Ei0, 1.0f);
                    float u11 = fmaf(nd.z, Ei1, 1.0f);
                    a0 = fmaf(fabsf(di0 - nd.y), __log2f(u00), a0);
                    a1 = fmaf(fabsf(di1 - nd.y), __log2f(u10), a1);
                    a2 = fmaf(fabsf(di0 - nd.w), __log2f(u01), a2);
                    a3 = fmaf(fabsf(di1 - nd.w), __log2f(u11), a3);
                }
                thread_sum += (a0 + a1) + (a2 + a3);
            }
            thread_sum *= norm;
        }
    }

    // ---- Deterministic block reduction ----
    {
        float ws = thread_sum;
        #pragma unroll
        for (int o = 16; o > 0; o >>= 1) ws += __shfl_down_sync(0xffffffffu, ws, o);
        if (lane == 0) red_f[wid] = ws;
        __syncthreads();
        if (wid == 0) {
            float v2 = (lane < NWARP) ? red_f[lane] : 0.0f;
            #pragma unroll
            for (int o = 4; o > 0; o >>= 1) v2 += __shfl_down_sync(0xffffffffu, v2, o);
            if (lane == 0) {
                g_partial[blockIdx.x] = v2;
                g_count[blockIdx.x]   = blk_count;
            }
        }
    }

    // ---- Fused finalize: last block reduces all partials in fixed order ----
    __threadfence();
    if (t == 0)
        s_last = (atomicAdd(&g_ticket, 1u) == (unsigned)(NBLK - 1));
    __syncthreads();

    if (s_last) {
        float fs = 0.0f;
        int   cs = 0;
        for (int idx = t; idx < NBLK; idx += BDIM) {
            fs += g_partial[idx];
            cs += g_count[idx];
        }
        #pragma unroll
        for (int o = 16; o > 0; o >>= 1) {
            fs += __shfl_down_sync(0xffffffffu, fs, o);
            cs += __shfl_down_sync(0xffffffffu, cs, o);
        }
        if (lane == 0) { red_f[wid] = fs; red_i[wid] = cs; }
        __syncthreads();
        if (t == 0) {
            float st = 0.0f; int ct = 0;
            #pragma unroll
            for (int w = 0; w < NWARP; w++) { st += red_f[w]; ct += red_i[w]; }
            out[0] = (ct > 0) ? (st / (float)ct) : 0.0f;
            g_ticket = 0;   // reset for next graph replay
        }
    }
}

extern "C" void kernel_launch(void* const* d_in, const int* in_sizes, int n_in,
                              void* d_out, int out_size)
{
    const float* scores = (const float*)d_in[0];
    const int*   rels   = (const int*)d_in[1];
    (void)in_sizes; (void)n_in; (void)out_size;

    lambdarank_fused<<<NBLK, BDIM>>>(scores, rels, (float*)d_out);
}

// round 6
// speedup vs baseline: 1.1552x; 1.1552x over previous
#include <cuda_runtime.h>

#define N_POS   1024
#define BDIM    256
#define SPLIT   8
#define NBLK    (64 * SPLIT)   // 512
#define KTOP    10
#define NWARP   (BDIM / 32)

__device__ float    g_partial[NBLK];
__device__ int      g_count[NBLK];
__device__ unsigned g_ticket;   // zero-init; reset to 0 by the last block each launch

// idcg prefix table: idcg(kk) = sum_{k=0}^{kk-1} 1/log2(k+2), kk = min(nrel, 10)
__constant__ float c_idcg[11] = {
    0.0f, 1.0f, 1.6309297535714574f, 2.1309297535714574f,
    2.5616063116448505f, 2.9484591188793920f, 3.3046663059874144f,
    3.6379996393207477f, 3.9534645161064764f, 4.2544945117704580f,
    4.5435593380883460f
};

__global__ __launch_bounds__(BDIM, 4) void lambdarank_fused(
    const float* __restrict__ scores, const int* __restrict__ rels,
    float* __restrict__ out)
{
    // float4-aligned compacted lists ((E, disc) pairs), zero-padded
    __shared__ float4 relSD4[(N_POS + 64) / 2];
    __shared__ float4 nonSD4[(N_POS + 64) / 2];
    __shared__ int    sh_cntR[NWARP], sh_baseR[NWARP], sh_baseN[NWARP];
    __shared__ int    sh_tot[2];
    __shared__ float  red_f[NWARP];
    __shared__ int    red_i[NWARP];
    __shared__ bool   s_last;

    float2* relSD = (float2*)relSD4;
    float2* nonSD = (float2*)nonSD4;

    const int b    = blockIdx.x >> 3;          // SPLIT = 8
    const int s    = blockIdx.x & (SPLIT - 1);
    const int t    = threadIdx.x;
    const int lane = t & 31;
    const int wid  = t >> 5;
    const unsigned lt_mask = (1u << lane) - 1u;

    // ---- Parallel deterministic stable compaction, direct from global ----
    unsigned masks[4];
    float    sc[4];
    {
        int cr = 0;
        #pragma unroll
        for (int it = 0; it < 4; it++) {
            int p = (wid << 7) + (it << 5) + lane;
            sc[it] = scores[b * N_POS + p];
            int r  = rels[b * N_POS + p];
            unsigned m = __ballot_sync(0xffffffffu, r != 0);
            masks[it] = m;
            cr += __popc(m);
        }
        if (lane == 0) sh_cntR[wid] = cr;
    }
    __syncthreads();
    if (t == 0) {
        int aR = 0, aN = 0;
        #pragma unroll
        for (int w = 0; w < NWARP; w++) {
            sh_baseR[w] = aR; sh_baseN[w] = aN;
            aR += sh_cntR[w]; aN += 128 - sh_cntR[w];
        }
        sh_tot[0] = aR; sh_tot[1] = aN;
    }
    __syncthreads();
    {
        int rb = sh_baseR[wid], nb = sh_baseN[wid];
        #pragma unroll
        for (int it = 0; it < 4; it++) {
            int p = (wid << 7) + (it << 5) + lane;
            unsigned m = masks[it];
            bool hit = (m >> lane) & 1u;
            float E  = __expf(hit ? -sc[it] : sc[it]);
            float d  = 1.0f / __log2f((float)p + 2.0f);   // DCG discount @ position p
            float2 v = make_float2(E, d);
            int preR = __popc(m & lt_mask);
            if (hit) relSD[rb + preR]          = v;
            else     nonSD[nb + (lane - preR)] = v;
            rb += __popc(m);
            nb += 32 - __popc(m);
        }
    }
    __syncthreads();

    const int nrel = sh_tot[0];
    const int nnon = sh_tot[1];

    // Zero padding: E=0 entries contribute exactly 0 (log2(1+0)=0)
    if (t < 64) {
        relSD[nrel + t] = make_float2(0.0f, 0.0f);
        nonSD[nnon + t] = make_float2(0.0f, 0.0f);
    }
    __syncthreads();

    float thread_sum = 0.0f;
    int   blk_count  = 0;

    if (nrel > 0 && nnon > 0) {
        const float idcg = c_idcg[(nrel < KTOP) ? nrel : KTOP];
        const float norm = 0.69314718055994531f / (idcg + 1e-8f);  // ln2/(idcg+eps)

        // Contiguous j-chunk per block; chunk multiple of 8 so full blocks have
        // trips4 % 4 == 0 (no remainder) and j0 is 16B-aligned.
        const int chunk = (((nnon + SPLIT - 1) >> 3) + 7) & ~7;
        const int j0    = s * chunk;
        int cntj  = nnon - j0;
        cntj  = (cntj < 0) ? 0 : ((cntj > chunk) ? chunk : cntj);
        blk_count = nrel * cntj;

        // trips4 rounded to multiple of 4; tail-block overread lands in zero-pad
        const int trips4 = ((((cntj + 1) >> 1) + 3) & ~3);
        const float4* nj4 = (const float4*)&nonSD[j0];

        if (trips4 > 0) {
            for (int ibase = 0; ibase < nrel; ibase += 2 * BDIM) {
                if (ibase + (wid << 6) >= nrel) continue;     // whole-warp tail skip
                const int ia = ibase + 2 * t;                 // zero-pad covers overhang
                const float4 rv = relSD4[ia >> 1];
                const float Ei0 = rv.x, di0 = rv.y;
                const float Ei1 = rv.z, di1 = rv.w;

                float a0 = 0.0f, a1 = 0.0f, a2 = 0.0f, a3 = 0.0f;
                for (int k = 0; k < trips4; k += 4) {
                    #pragma unroll
                    for (int u = 0; u < 4; u++) {
                        const float4 nd = nj4[k + u];         // 2 j's per LDS.128 (broadcast)
                        float u00 = fmaf(nd.x, Ei0, 1.0f);
                        float u10 = fmaf(nd.x, Ei1, 1.0f);
                        float u01 = fmaf(nd.z, Ei0, 1.0f);
                        float u11 = fmaf(nd.z, Ei1, 1.0f);
                        a0 = fmaf(fabsf(di0 - nd.y), __log2f(u00), a0);
                        a1 = fmaf(fabsf(di1 - nd.y), __log2f(u10), a1);
                        a2 = fmaf(fabsf(di0 - nd.w), __log2f(u01), a2);
                        a3 = fmaf(fabsf(di1 - nd.w), __log2f(u11), a3);
                    }
                }
                thread_sum += (a0 + a1) + (a2 + a3);
            }
            thread_sum *= norm;
        }
    }

    // ---- Deterministic block reduction ----
    {
        float ws = thread_sum;
        #pragma unroll
        for (int o = 16; o > 0; o >>= 1) ws += __shfl_down_sync(0xffffffffu, ws, o);
        if (lane == 0) red_f[wid] = ws;
        __syncthreads();
        if (wid == 0) {
            float v2 = (lane < NWARP) ? red_f[lane] : 0.0f;
            #pragma unroll
            for (int o = 4; o > 0; o >>= 1) v2 += __shfl_down_sync(0xffffffffu, v2, o);
            if (lane == 0) {
                g_partial[blockIdx.x] = v2;
                g_count[blockIdx.x]   = blk_count;
            }
        }
    }

    // ---- Fused finalize: last block reduces all partials in fixed order ----
    __threadfence();
    if (t == 0)
        s_last = (atomicAdd(&g_ticket, 1u) == (unsigned)(NBLK - 1));
    __syncthreads();

    if (s_last) {
        float fs = 0.0f;
        int   cs = 0;
        for (int idx = t; idx < NBLK; idx += BDIM) {
            fs += g_partial[idx];
            cs += g_count[idx];
        }
        #pragma unroll
        for (int o = 16; o > 0; o >>= 1) {
            fs += __shfl_down_sync(0xffffffffu, fs, o);
            cs += __shfl_down_sync(0xffffffffu, cs, o);
        }
        if (lane == 0) { red_f[wid] = fs; red_i[wid] = cs; }
        __syncthreads();
        if (t == 0) {
            float st = 0.0f; int ct = 0;
            #pragma unroll
            for (int w = 0; w < NWARP; w++) { st += red_f[w]; ct += red_i[w]; }
            out[0] = (ct > 0) ? (st / (float)ct) : 0.0f;
            g_ticket = 0;   // reset for next graph replay
        }
    }
}

extern "C" void kernel_launch(void* const* d_in, const int* in_sizes, int n_in,
                              void* d_out, int out_size)
{
    const float* scores = (const float*)d_in[0];
    const int*   rels   = (const int*)d_in[1];
    (void)in_sizes; (void)n_in; (void)out_size;

    lambdarank_fused<<<NBLK, BDIM>>>(scores, rels, (float*)d_out);
}